// round 2
// baseline (speedup 1.0000x reference)
#include <cuda_runtime.h>
#include <cstddef>

#define N_NODES 100000
#define N_EDGES 1600000
#define D 128

// Scratch: device globals (allocation-free per harness rules). 51.2 MB each.
__device__ float g_agg[(size_t)N_NODES * D];
__device__ float g_h[(size_t)N_NODES * D];

// ---------------------------------------------------------------------------
// Kernel 1: zero the aggregation buffer (float4 vectorized).
// ---------------------------------------------------------------------------
__global__ void zero_kernel(float4* __restrict__ p, int n4) {
    int i = blockIdx.x * blockDim.x + threadIdx.x;
    if (i < n4) p[i] = make_float4(0.f, 0.f, 0.f, 0.f);
}

// ---------------------------------------------------------------------------
// Kernel 2: edge scatter. One warp per edge; 32 lanes x float4 = 128 floats.
// Gather x[src] (L2-resident), vector-reduce into agg[dst] via red.global.v4.
// NOTE: edge_index is int32 (JAX x64 disabled -> jnp.int64 materializes as
// int32). Reading it as int64 was the R1 illegal-access bug.
// ---------------------------------------------------------------------------
__global__ void scatter_kernel(const float* __restrict__ x,
                               const int* __restrict__ ei,
                               float* __restrict__ agg) {
    int gwarp = (blockIdx.x * blockDim.x + threadIdx.x) >> 5;
    int lane  = threadIdx.x & 31;
    int nwarp = (gridDim.x * blockDim.x) >> 5;
    for (int e = gwarp; e < N_EDGES; e += nwarp) {
        int s = __ldg(&ei[e]);
        int d = __ldg(&ei[N_EDGES + e]);
        float4 v = __ldg((const float4*)(x + (size_t)s * D) + lane);
        float* dst = agg + (size_t)d * D + lane * 4;
        asm volatile("red.global.add.v4.f32 [%0], {%1, %2, %3, %4};"
                     :: "l"(dst), "f"(v.x), "f"(v.y), "f"(v.z), "f"(v.w)
                     : "memory");
    }
}

// ---------------------------------------------------------------------------
// Kernels 3/4: tiled SGEMM  C = act(A_eff @ W + bias)
//   FUSE:  A_eff = (1+eps)*A + A2   (GIN combine, fused into the A-tile load)
//   RELU:  apply relu in epilogue
// Tile: BM=128 rows x full N=128 x full K=128. 256 threads, 8x8 microtile
// with rows m = (tid&15)+16*i, cols n = (tid>>4)+16*j.
// As is row-major with LDA=129: all LDS are conflict-free (bank=(m+k)%32
// distinct over unique lanes; duplicate lanes broadcast). Ws reads broadcast.
// Epilogue staged through smem for coalesced float4 global stores.
// ---------------------------------------------------------------------------
#define BM 128
#define LDA 129
#define GEMM_THREADS 256
#define SMEM_BYTES ((BM * LDA + D * D) * 4)

template<bool FUSE, bool RELU>
__global__ void __launch_bounds__(GEMM_THREADS, 1)
gemm_kernel(const float* __restrict__ A,
            const float* __restrict__ A2,
            const float* __restrict__ epsp,
            const float* __restrict__ W,
            const float* __restrict__ bias,
            float* __restrict__ C,
            int n_rows) {
    extern __shared__ float smem[];
    float* As = smem;                // [BM][LDA]
    float* Ws = smem + BM * LDA;     // [D][D]

    const int tid  = threadIdx.x;
    const int row0 = blockIdx.x * BM;
    float scale = 1.0f;
    if (FUSE) scale = 1.0f + __ldg(epsp);

    // Load W tile (whole 128x128, row-major [k][n]), float4 coalesced.
    {
        const float4* Wg = (const float4*)W;
        float4* Wsh = (float4*)Ws;
        #pragma unroll
        for (int i = 0; i < 16; i++)
            Wsh[tid + i * 256] = __ldg(&Wg[tid + i * 256]);
    }
    // Load A tile, scalar coalesced, store row-major As[m][k] (LDA=129,
    // conflict-free: bank = (m + k) % 32, lanes share m with k contiguous).
    {
        #pragma unroll
        for (int i = 0; i < 64; i++) {
            int idx = tid + i * 256;   // 0..16383
            int m = idx >> 7;
            int k = idx & 127;
            int r = row0 + m;
            float v = 0.f;
            if (r < n_rows) {
                v = __ldg(&A[(size_t)r * D + k]);
                if (FUSE) v = fmaf(scale, v, __ldg(&A2[(size_t)r * D + k]));
            }
            As[m * LDA + k] = v;
        }
    }
    __syncthreads();

    const int tm = tid & 15;
    const int tn = tid >> 4;

    float breg[8];
    #pragma unroll
    for (int j = 0; j < 8; j++) breg[j] = __ldg(&bias[tn + 16 * j]);

    float acc[8][8];
    #pragma unroll
    for (int i = 0; i < 8; i++)
        #pragma unroll
        for (int j = 0; j < 8; j++) acc[i][j] = 0.f;

    #pragma unroll 4
    for (int k = 0; k < D; k++) {
        float a[8], b[8];
        #pragma unroll
        for (int i = 0; i < 8; i++) a[i] = As[(tm + 16 * i) * LDA + k];
        #pragma unroll
        for (int j = 0; j < 8; j++) b[j] = Ws[k * D + (tn + 16 * j)];
        #pragma unroll
        for (int i = 0; i < 8; i++)
            #pragma unroll
            for (int j = 0; j < 8; j++)
                acc[i][j] = fmaf(a[i], b[j], acc[i][j]);
    }

    // Epilogue: bias (+relu), stage into smem (reuse As), coalesced f4 stores.
    __syncthreads();
    #pragma unroll
    for (int i = 0; i < 8; i++) {
        #pragma unroll
        for (int j = 0; j < 8; j++) {
            float v = acc[i][j] + breg[j];
            if (RELU) v = fmaxf(v, 0.f);
            As[(tm + 16 * i) * LDA + (tn + 16 * j)] = v;
        }
    }
    __syncthreads();
    #pragma unroll
    for (int i = 0; i < 16; i++) {
        int idx = tid + i * 256;   // 0..4095 float4s
        int m  = idx >> 5;
        int c4 = idx & 31;
        int r = row0 + m;
        if (r < n_rows) {
            const float* src = As + m * LDA + c4 * 4;
            float4 v = make_float4(src[0], src[1], src[2], src[3]);
            ((float4*)(C + (size_t)r * D))[c4] = v;
        }
    }
}

// ---------------------------------------------------------------------------
extern "C" void kernel_launch(void* const* d_in, const int* in_sizes, int n_in,
                              void* d_out, int out_size) {
    const float* x    = (const float*)d_in[0];
    const int*   ei   = (const int*)d_in[1];
    const float* eps  = (const float*)d_in[2];
    const float* W1   = (const float*)d_in[3];
    const float* b1   = (const float*)d_in[4];
    const float* W2   = (const float*)d_in[5];
    const float* b2   = (const float*)d_in[6];
    float*       out  = (float*)d_out;

    float* agg = nullptr;
    float* h   = nullptr;
    cudaGetSymbolAddress((void**)&agg, g_agg);
    cudaGetSymbolAddress((void**)&h,   g_h);

    // Allow >48KB dynamic smem for the GEMMs (capture-safe host API).
    cudaFuncSetAttribute(gemm_kernel<true, true>,
                         cudaFuncAttributeMaxDynamicSharedMemorySize, SMEM_BYTES);
    cudaFuncSetAttribute(gemm_kernel<false, false>,
                         cudaFuncAttributeMaxDynamicSharedMemorySize, SMEM_BYTES);

    // 1. agg = 0
    {
        int n4 = N_NODES * D / 4;
        zero_kernel<<<(n4 + 255) / 256, 256>>>((float4*)agg, n4);
    }
    // 2. agg[dst] += x[src]
    scatter_kernel<<<2048, 256>>>(x, ei, agg);

    // 3. h = relu(((1+eps)*x + agg) @ W1 + b1)
    int nblk = (N_NODES + BM - 1) / BM;
    gemm_kernel<true, true><<<nblk, GEMM_THREADS, SMEM_BYTES>>>(
        x, agg, eps, W1, b1, h, N_NODES);

    // 4. out = h @ W2 + b2
    gemm_kernel<false, false><<<nblk, GEMM_THREADS, SMEM_BYTES>>>(
        h, nullptr, nullptr, W2, b2, out, N_NODES);
}

// round 4
// speedup vs baseline: 1.5678x; 1.5678x over previous
#include <cuda_runtime.h>
#include <cuda_bf16.h>
#include <cstdint>
#include <cstddef>

#define N_NODES 100000
#define N_EDGES 1600000
#define D 128
#define BM 128

// Scratch: device globals (allocation-free harness rules).
__device__ float g_agg[(size_t)N_NODES * D];
__device__ float g_h[(size_t)N_NODES * D];
__device__ __nv_bfloat16 g_wbh[2][D * D];   // bf16 hi of W^T  [n][k]
__device__ __nv_bfloat16 g_wbl[2][D * D];   // bf16 lo residual of W^T  [n][k]

// ---------------------------------------------------------------------------
// Helpers
// ---------------------------------------------------------------------------
__device__ __forceinline__ uint32_t smem_u32(const void* p) {
    uint32_t a;
    asm("{ .reg .u64 t; cvta.to.shared.u64 t, %1; cvt.u32.u64 %0, t; }"
        : "=r"(a) : "l"(p));
    return a;
}
__device__ __forceinline__ uint32_t pack_bf2(float a, float b) {
    uint16_t ua = __bfloat16_as_ushort(__float2bfloat16(a));
    uint16_t ub = __bfloat16_as_ushort(__float2bfloat16(b));
    return (uint32_t)ua | ((uint32_t)ub << 16);
}
__device__ __forceinline__ float bf_res(float v) {
    return v - __bfloat162float(__float2bfloat16(v));
}
__device__ __forceinline__ void ldm4(uint32_t& r0, uint32_t& r1,
                                     uint32_t& r2, uint32_t& r3, uint32_t addr) {
    asm volatile("ldmatrix.sync.aligned.m8n8.x4.shared.b16 {%0,%1,%2,%3}, [%4];"
                 : "=r"(r0), "=r"(r1), "=r"(r2), "=r"(r3) : "r"(addr));
}
__device__ __forceinline__ void mma_bf16(float* c, const uint32_t* a,
                                         const uint32_t* b) {
    asm volatile(
        "mma.sync.aligned.m16n8k16.row.col.f32.bf16.bf16.f32 "
        "{%0,%1,%2,%3}, {%4,%5,%6,%7}, {%8,%9}, {%0,%1,%2,%3};"
        : "+f"(c[0]), "+f"(c[1]), "+f"(c[2]), "+f"(c[3])
        : "r"(a[0]), "r"(a[1]), "r"(a[2]), "r"(a[3]), "r"(b[0]), "r"(b[1]));
}

// ---------------------------------------------------------------------------
// prep: split W into bf16 hi/lo, transposed to [n][k].
// ---------------------------------------------------------------------------
__global__ void prep_w(const float* __restrict__ W1, const float* __restrict__ W2) {
    int idx = blockIdx.x * blockDim.x + threadIdx.x;   // 0..16383
    int which = blockIdx.y;
    const float* W = which ? W2 : W1;
    int k = idx >> 7, n = idx & 127;
    float v = __ldg(&W[k * D + n]);
    g_wbh[which][n * D + k] = __float2bfloat16(v);
    g_wbl[which][n * D + k] = __float2bfloat16(bf_res(v));
}

// ---------------------------------------------------------------------------
// zero + scatter (unchanged from R2-pass).
// ---------------------------------------------------------------------------
__global__ void zero_kernel(float4* __restrict__ p, int n4) {
    int i = blockIdx.x * blockDim.x + threadIdx.x;
    if (i < n4) p[i] = make_float4(0.f, 0.f, 0.f, 0.f);
}
__global__ void scatter_kernel(const float* __restrict__ x,
                               const int* __restrict__ ei,
                               float* __restrict__ agg) {
    int gwarp = (blockIdx.x * blockDim.x + threadIdx.x) >> 5;
    int lane = threadIdx.x & 31;
    int nwarp = (gridDim.x * blockDim.x) >> 5;
    for (int e = gwarp; e < N_EDGES; e += nwarp) {
        int s = __ldg(&ei[e]);
        int d = __ldg(&ei[N_EDGES + e]);
        float4 v = __ldg((const float4*)(x + (size_t)s * D) + lane);
        float* dst = agg + (size_t)d * D + lane * 4;
        asm volatile("red.global.add.v4.f32 [%0], {%1, %2, %3, %4};"
                     :: "l"(dst), "f"(v.x), "f"(v.y), "f"(v.z), "f"(v.w)
                     : "memory");
    }
}

// ---------------------------------------------------------------------------
// bf16x3-split tensor-core GEMM:  C = act(A_eff @ W + bias)
//   FUSE: A_eff = (1+eps)*A + A2 ; RELU epilogue.
// CTA tile 128x128xK128. 8 warps in 4(m) x 2(n): each warp 32 rows x 64 cols.
// Operands staged in smem with 272B row pitch (ldmatrix conflict-free).
// D = Ah*Wh + Ah*Wl + Al*Wh  (fp32 acc) -> ~1e-6 rel err.
// ---------------------------------------------------------------------------
#define PL 272                       // smem row pitch, bytes (136 bf16)
#define SM_AH 1024
#define SM_AL (SM_AH + 128 * PL)     // 35840
#define SM_BH (SM_AL + 128 * PL)     // 70656
#define SM_BL (SM_BH + 128 * PL)     // 105472
#define SMEM_TOT (SM_BL + 128 * PL)  // 140288

template<bool FUSE, bool RELU>
__global__ void __launch_bounds__(256, 1)
gin_gemm(const float* __restrict__ A, const float* __restrict__ A2,
         const float* __restrict__ epsp,
         const __nv_bfloat16* __restrict__ Bh, const __nv_bfloat16* __restrict__ Bl,
         const float* __restrict__ bias, float* __restrict__ C, int n_rows) {
    extern __shared__ char sm[];
    const int tid = threadIdx.x;
    const int row0 = blockIdx.x * BM;

    float* sb_bias = (float*)sm;
    if (tid < 128) sb_bias[tid] = __ldg(&bias[tid]);

    // ---- Stage A (fused GIN combine) -> bf16 hi/lo planes ----
    {
        float scale = FUSE ? (1.0f + __ldg(epsp)) : 1.0f;
        #pragma unroll
        for (int i = 0; i < 16; i++) {
            int idx = tid + i * 256;      // 0..4095 float4s
            int row = idx >> 5, c4 = idx & 31;
            int r = row0 + row;
            float4 v = make_float4(0.f, 0.f, 0.f, 0.f);
            if (r < n_rows) {
                v = __ldg((const float4*)(A + (size_t)r * D) + c4);
                if (FUSE) {
                    float4 w = __ldg((const float4*)(A2 + (size_t)r * D) + c4);
                    v.x = fmaf(scale, v.x, w.x);
                    v.y = fmaf(scale, v.y, w.y);
                    v.z = fmaf(scale, v.z, w.z);
                    v.w = fmaf(scale, v.w, w.w);
                }
            }
            uint2 hu, lu;
            hu.x = pack_bf2(v.x, v.y);
            hu.y = pack_bf2(v.z, v.w);
            lu.x = pack_bf2(bf_res(v.x), bf_res(v.y));
            lu.y = pack_bf2(bf_res(v.z), bf_res(v.w));
            *(uint2*)(sm + SM_AH + row * PL + c4 * 8) = hu;
            *(uint2*)(sm + SM_AL + row * PL + c4 * 8) = lu;
        }
    }
    // ---- Stage B (pre-split W^T [n][k]) ----
    {
        #pragma unroll
        for (int i = 0; i < 8; i++) {
            int idx = tid + i * 256;      // 0..2047 uint4s
            int n = idx >> 4, c16 = idx & 15;
            *(uint4*)(sm + SM_BH + n * PL + c16 * 16) = __ldg((const uint4*)Bh + idx);
            *(uint4*)(sm + SM_BL + n * PL + c16 * 16) = __ldg((const uint4*)Bl + idx);
        }
    }
    __syncthreads();

    const int wid = tid >> 5, lane = tid & 31;
    const int wm = wid & 3, wn = wid >> 2;
    const uint32_t sbase = smem_u32(sm);

    // ldmatrix base addresses (constant over k-steps; advance by 32B/step)
    const int i8 = lane & 7;
    // A: matrix j: m_off=(j&1)*8, k_off=(j>>1)*8  -> frag order a0..a3
    const int jA_m = ((lane >> 3) & 1) * 8;
    const int jA_k = (lane >> 4) * 8;
    uint32_t aH0 = sbase + SM_AH + (uint32_t)(wm * 32 + jA_m + i8) * PL + jA_k * 2;
    uint32_t aH1 = aH0 + 16 * PL;
    uint32_t aL0 = aH0 + (SM_AL - SM_AH);
    uint32_t aL1 = aL0 + 16 * PL;
    // B: matrix j: k_off=(j&1)*8, n_off=(j>>1)*8 -> (b0,b1) for natoms 2g,2g+1
    const int jB_k = ((lane >> 3) & 1) * 8;
    const int jB_n = (lane >> 4) * 8;
    uint32_t bH[4], bL[4];
    #pragma unroll
    for (int g = 0; g < 4; g++) {
        uint32_t nrow = (uint32_t)(wn * 64 + g * 16 + jB_n + i8);
        bH[g] = sbase + SM_BH + nrow * PL + jB_k * 2;
        bL[g] = bH[g] + (SM_BL - SM_BH);
    }

    float acc[2][8][4];
    #pragma unroll
    for (int m = 0; m < 2; m++)
        #pragma unroll
        for (int n = 0; n < 8; n++)
            #pragma unroll
            for (int q = 0; q < 4; q++) acc[m][n][q] = 0.f;

    #pragma unroll
    for (int ks = 0; ks < 8; ks++) {
        const uint32_t ko = ks * 32;   // 16 bf16 = 32 bytes
        uint32_t ah[2][4], al[2][4], bh[8][2], bl[8][2];
        ldm4(ah[0][0], ah[0][1], ah[0][2], ah[0][3], aH0 + ko);
        ldm4(ah[1][0], ah[1][1], ah[1][2], ah[1][3], aH1 + ko);
        ldm4(al[0][0], al[0][1], al[0][2], al[0][3], aL0 + ko);
        ldm4(al[1][0], al[1][1], al[1][2], al[1][3], aL1 + ko);
        #pragma unroll
        for (int g = 0; g < 4; g++) {
            ldm4(bh[2 * g][0], bh[2 * g][1], bh[2 * g + 1][0], bh[2 * g + 1][1],
                 bH[g] + ko);
            ldm4(bl[2 * g][0], bl[2 * g][1], bl[2 * g + 1][0], bl[2 * g + 1][1],
                 bL[g] + ko);
        }
        #pragma unroll
        for (int n = 0; n < 8; n++) {
            #pragma unroll
            for (int m = 0; m < 2; m++) {
                mma_bf16(acc[m][n], ah[m], bh[n]);   // Ah*Wh
                mma_bf16(acc[m][n], ah[m], bl[n]);   // Ah*Wl
                mma_bf16(acc[m][n], al[m], bh[n]);   // Al*Wh
            }
        }
    }

    // ---- Epilogue: bias (+relu), direct float2 stores ----
    const int tig = lane & 3, grp = lane >> 2;
    #pragma unroll
    for (int m = 0; m < 2; m++) {
        int r = row0 + wm * 32 + m * 16 + grp;
        #pragma unroll
        for (int n = 0; n < 8; n++) {
            int col = wn * 64 + n * 8 + tig * 2;
            float b0 = sb_bias[col], b1 = sb_bias[col + 1];
            float2 v0 = make_float2(acc[m][n][0] + b0, acc[m][n][1] + b1);
            float2 v1 = make_float2(acc[m][n][2] + b0, acc[m][n][3] + b1);
            if (RELU) {
                v0.x = fmaxf(v0.x, 0.f); v0.y = fmaxf(v0.y, 0.f);
                v1.x = fmaxf(v1.x, 0.f); v1.y = fmaxf(v1.y, 0.f);
            }
            if (r < n_rows)     *(float2*)(C + (size_t)r * D + col) = v0;
            if (r + 8 < n_rows) *(float2*)(C + (size_t)(r + 8) * D + col) = v1;
        }
    }
}

// ---------------------------------------------------------------------------
extern "C" void kernel_launch(void* const* d_in, const int* in_sizes, int n_in,
                              void* d_out, int out_size) {
    const float* x   = (const float*)d_in[0];
    const int*   ei  = (const int*)d_in[1];
    const float* eps = (const float*)d_in[2];
    const float* W1  = (const float*)d_in[3];
    const float* b1  = (const float*)d_in[4];
    const float* W2  = (const float*)d_in[5];
    const float* b2  = (const float*)d_in[6];
    float*       out = (float*)d_out;

    float *agg, *h;
    __nv_bfloat16 *wbh, *wbl;
    cudaGetSymbolAddress((void**)&agg, g_agg);
    cudaGetSymbolAddress((void**)&h, g_h);
    cudaGetSymbolAddress((void**)&wbh, g_wbh);
    cudaGetSymbolAddress((void**)&wbl, g_wbl);

    cudaFuncSetAttribute(gin_gemm<true, true>,
                         cudaFuncAttributeMaxDynamicSharedMemorySize, SMEM_TOT);
    cudaFuncSetAttribute(gin_gemm<false, false>,
                         cudaFuncAttributeMaxDynamicSharedMemorySize, SMEM_TOT);

    // W split/transpose
    prep_w<<<dim3(64, 2), 256>>>(W1, W2);

    // agg = 0 ; agg[dst] += x[src]
    int n4 = N_NODES * D / 4;
    zero_kernel<<<(n4 + 255) / 256, 256>>>((float4*)agg, n4);
    scatter_kernel<<<2048, 256>>>(x, ei, agg);

    int nblk = (N_NODES + BM - 1) / BM;   // 782
    // h = relu(((1+eps)x + agg) @ W1 + b1)
    gin_gemm<true, true><<<nblk, 256, SMEM_TOT>>>(
        x, agg, eps, wbh, wbl, b1, h, N_NODES);
    // out = h @ W2 + b2
    gin_gemm<false, false><<<nblk, 256, SMEM_TOT>>>(
        h, h, nullptr, wbh + D * D, wbl + D * D, b2, out, N_NODES);
}